// round 16
// baseline (speedup 1.0000x reference)
#include <cuda_runtime.h>
#include <math.h>
#include <stdint.h>

#define N_NODES 200000
#define E_EDGES 800000
#define NBATCH  16
#define PK      208   // 193 padded to multiple of 16
#define NBLK    782   // ceil(N_NODES / 256)

// ---------------- scratch (static; no cudaMalloc) ----------------
__device__ __align__(16) float    g_x   [(size_t)N_NODES * 128];
__device__ __align__(16) float    g_aggA[(size_t)N_NODES * 64];
__device__ __align__(16) float    g_aggB[(size_t)N_NODES * 64];
__device__ __align__(16) float    g_y   [(size_t)N_NODES * 64];
__device__ __align__(16) float    g_rn  [N_NODES];
__device__ __align__(16) float    g_deg [N_NODES];
__device__ __align__(16) int      g_degi[N_NODES];
__device__ __align__(16) int      g_bsum[1024];
__device__ __align__(16) int      g_off [N_NODES + 1];
__device__ __align__(16) int      g_cur [N_NODES];
__device__ __align__(16) int      g_elist[E_EDGES];
__device__ __align__(16) unsigned g_gmax[NBATCH * 64];
__device__ __align__(16) float    g_gsum[NBATCH * 64];
__device__ __align__(16) float    g_cnt [NBATCH];

// ---------------- helpers ----------------
__device__ __forceinline__ unsigned fenc(float f) {
    unsigned u = __float_as_uint(f);
    return (u & 0x80000000u) ? ~u : (u | 0x80000000u);
}
__device__ __forceinline__ float fdec(unsigned u) {
    return (u & 0x80000000u) ? __uint_as_float(u & 0x7FFFFFFFu) : __uint_as_float(~u);
}

__global__ void init_kernel() {   // zero degi + pool accumulators (one launch)
    int i = blockIdx.x * blockDim.x + threadIdx.x;
    if (i < N_NODES) g_degi[i] = 0;
    if (i < NBATCH * 64) { g_gmax[i] = 0u; g_gsum[i] = 0.f; }
    if (i < NBATCH) g_cnt[i] = 0.f;
}

__global__ void deg_kernel(const int* __restrict__ dst) {
    int e = blockIdx.x * blockDim.x + threadIdx.x;
    if (e < E_EDGES) atomicAdd(&g_degi[dst[e]], 1);
}
__global__ void deginv_kernel() {
    int n = blockIdx.x * blockDim.x + threadIdx.x;
    if (n < N_NODES) g_deg[n] = 1.f / (float)max(g_degi[n], 1);
}

// ---------------- CSR build: 3-kernel scan + fill ----------------
__global__ void scan1_kernel() {
    __shared__ int s[256];
    int t = threadIdx.x, i = blockIdx.x * 256 + t;
    s[t] = (i < N_NODES) ? g_degi[i] : 0;
    __syncthreads();
#pragma unroll
    for (int off = 128; off > 0; off >>= 1) {
        if (t < off) s[t] += s[t + off];
        __syncthreads();
    }
    if (t == 0) g_bsum[blockIdx.x] = s[0];
}

__global__ void scan2_kernel() {
    __shared__ int sa[1024], sb[1024];
    int t = threadIdx.x;
    int v = (t < NBLK) ? g_bsum[t] : 0;
    sa[t] = v;
    __syncthreads();
    int* cur = sa; int* nxt = sb;
#pragma unroll
    for (int off = 1; off < 1024; off <<= 1) {
        int x = cur[t];
        if (t >= off) x += cur[t - off];
        nxt[t] = x;
        __syncthreads();
        int* tmp = cur; cur = nxt; nxt = tmp;
    }
    if (t < NBLK) g_bsum[t] = cur[t] - v;
}

__global__ void scan3_kernel() {
    __shared__ int sa[256], sb[256];
    int t = threadIdx.x, i = blockIdx.x * 256 + t;
    int v = (i < N_NODES) ? g_degi[i] : 0;
    sa[t] = v;
    __syncthreads();
    int* cur = sa; int* nxt = sb;
#pragma unroll
    for (int off = 1; off < 256; off <<= 1) {
        int x = cur[t];
        if (t >= off) x += cur[t - off];
        nxt[t] = x;
        __syncthreads();
        int* tmp = cur; cur = nxt; nxt = tmp;
    }
    int excl = cur[t] - v + g_bsum[blockIdx.x];
    if (i < N_NODES) { g_off[i] = excl; g_cur[i] = excl; }
    if (i == 0) g_off[N_NODES] = E_EDGES;
}

__global__ void fill_kernel(const int* __restrict__ src, const int* __restrict__ dst) {
    int e = blockIdx.x * blockDim.x + threadIdx.x;
    if (e >= E_EDGES) return;
    int d = dst[e];
    int pos = atomicAdd(&g_cur[d], 1);
    g_elist[pos] = src[e];
}

// ---------------- tf32 split helpers ----------------
__device__ __forceinline__ void split_tf32(float x, uint32_t& h, uint32_t& l) {
    uint32_t hb;
    asm("cvt.rna.tf32.f32 %0, %1;" : "=r"(hb) : "f"(x));
    h = hb;
    l = __float_as_uint(x - __uint_as_float(hb));
}

__device__ __forceinline__ void mma8(float* c, const uint32_t* a, const uint32_t* b) {
    asm("mma.sync.aligned.m16n8k8.row.col.f32.tf32.tf32.f32 "
        "{%0,%1,%2,%3}, {%4,%5,%6,%7}, {%8,%9}, {%0,%1,%2,%3};"
        : "+f"(c[0]), "+f"(c[1]), "+f"(c[2]), "+f"(c[3])
        : "r"(a[0]), "r"(a[1]), "r"(a[2]), "r"(a[3]), "r"(b[0]), "r"(b[1]));
}

// ---------------- fragment-major SMEM slot maps ----------------
// A tile 16(k) x 64(m): frag a[4] = {A[kb][r], A[kb][r+8], A[kb+4][r], A[kb+4][r+8]}
//   kb = kk*8 + tig, r = wm2*32 + mi*16 + gid; consuming lane = gid*4+tig.
// Layout Afrag[wm2][kk][mi][lane][4]  (1024 uint32 per 16x64 tile)
__device__ __forceinline__ int slotA(int k, int m) {
    int lane = (m & 7) * 4 + (k & 3);
    int j = (((k >> 2) & 1) << 1) | ((m >> 3) & 1);
    return ((((m >> 5) * 2 + (k >> 3)) * 2 + ((m >> 4) & 1)) * 32 + lane) * 4 + j;
}
// B tile 16(k) x BN(n): frag b[2] = {B[kb][n], B[kb+4][n]}, n = n8*8 + gid.
// Layout Bfrag[n8][kk][lane][2]   (BN*16 uint32 per tile)
__device__ __forceinline__ int slotB(int k, int n) {
    int lane = (n & 7) * 4 + (k & 3);
    return (((n >> 3) * 2 + (k >> 3)) * 32 + lane) * 2 + ((k >> 2) & 1);
}

// one BK=16 tile of split-tf32 mma; block tile 64 x BN, 8 warps as 2M x 4N.
// A/B pre-split AND pre-arranged fragment-major: A-frag = 1 LDS.128, B-frag = 1 LDS.64.
template<int NI>
__device__ __forceinline__ void mma_ktile(const uint32_t* __restrict__ Ah,
                                          const uint32_t* __restrict__ Al,
                                          const uint32_t* __restrict__ Bh,
                                          const uint32_t* __restrict__ Bl,
                                          int wm2, int wn8, int lane,
                                          float (&acc)[2][NI][4]) {
#pragma unroll
    for (int kk = 0; kk < 2; kk++) {
        uint32_t aH[2][4], aL[2][4];
#pragma unroll
        for (int mi = 0; mi < 2; mi++) {
            int base = (((wm2 * 2 + kk) * 2 + mi) * 32 + lane) * 4;
            uint4 h4 = *reinterpret_cast<const uint4*>(Ah + base);
            uint4 l4 = *reinterpret_cast<const uint4*>(Al + base);
            aH[mi][0] = h4.x; aH[mi][1] = h4.y; aH[mi][2] = h4.z; aH[mi][3] = h4.w;
            aL[mi][0] = l4.x; aL[mi][1] = l4.y; aL[mi][2] = l4.z; aL[mi][3] = l4.w;
        }
#pragma unroll
        for (int ni = 0; ni < NI; ni++) {
            int bb = (((wn8 + ni) * 2 + kk) * 32 + lane) * 2;
            uint2 h2 = *reinterpret_cast<const uint2*>(Bh + bb);
            uint2 l2 = *reinterpret_cast<const uint2*>(Bl + bb);
            uint32_t bh[2] = {h2.x, h2.y};
            uint32_t bl[2] = {l2.x, l2.y};
#pragma unroll
            for (int mi = 0; mi < 2; mi++) {
                mma8(acc[mi][ni], aH[mi], bh);
                mma8(acc[mi][ni], aH[mi], bl);
                mma8(acc[mi][ni], aL[mi], bh);
            }
        }
    }
}

// ---------------- fused feature gather ----------------
__device__ __forceinline__ float gatherA(const float* __restrict__ nf, const float* __restrict__ cfgf,
                                         const int* __restrict__ opc,
                                         const float* __restrict__ opE, const float* __restrict__ tyE,
                                         int n, int c) {
    if (c < 139) return nf[(size_t)n * 140 + c];
    if (c < 143) { int ty = (int)nf[(size_t)n * 140 + 139]; return tyE[ty * 4 + (c - 139)]; }
    if (c < 175) return opE[opc[n] * 32 + (c - 143)];
    if (c < 193) return cfgf[(size_t)n * 18 + (c - 175)];
    return 0.f;
}

// ---------------- initial GEMM: x = relu(gather(feat) @ W + b), (N,128) ----
__global__ __launch_bounds__(256, 2) void gemm_initial(
    const float* __restrict__ nf, const float* __restrict__ cfgf, const int* __restrict__ opc,
    const float* __restrict__ opE, const float* __restrict__ tyE,
    const float* __restrict__ lin_w,
    const float* __restrict__ bias, float* __restrict__ X)
{
    constexpr int BN = 128, NI = 4;
    __shared__ uint32_t Ah[16 * 64];
    __shared__ uint32_t Al[16 * 64];
    __shared__ uint32_t Bh[16 * BN];
    __shared__ uint32_t Bl[16 * BN];
    const int tid = threadIdx.x, lane = tid & 31, wid = tid >> 5;
    const int gid = lane >> 2, tig = lane & 3;
    const int wm2 = wid & 1, wn = (wid >> 1) * (BN / 4);
    const int wn8 = wn >> 3;
    const int m0 = blockIdx.x * 64;
    float acc[2][NI][4] = {};

    for (int k0 = 0; k0 < PK; k0 += 16) {
#pragma unroll
        for (int i = 0; i < 4; i++) {
            int idx = tid + i * 256; int m = idx >> 4, k = idx & 15;
            int mg = m0 + m, kg = k0 + k;
            float v = (mg < N_NODES) ? gatherA(nf, cfgf, opc, opE, tyE, mg, kg) : 0.f;
            uint32_t h, l; split_tf32(v, h, l);
            int s = slotA(k, m);
            Ah[s] = h; Al[s] = l;
        }
#pragma unroll
        for (int i = 0; i < 8; i++) {
            int idx = tid + i * 256; int k = idx / BN, n = idx % BN;
            int kg = k0 + k;
            float v = (kg < 193) ? lin_w[kg * 128 + n] : 0.f;
            uint32_t h, l; split_tf32(v, h, l);
            int s = slotB(k, n);
            Bh[s] = h; Bl[s] = l;
        }
        __syncthreads();
        mma_ktile<NI>(Ah, Al, Bh, Bl, wm2, wn8, lane, acc);
        __syncthreads();
    }

#pragma unroll
    for (int mi = 0; mi < 2; mi++) {
        int r0 = m0 + wm2 * 32 + mi * 16 + gid;
#pragma unroll
        for (int ni = 0; ni < NI; ni++) {
            int c = wn + ni * 8 + 2 * tig;
            float b0 = bias[c], b1 = bias[c + 1];
            if (r0 < N_NODES) {
                float2 o = make_float2(fmaxf(acc[mi][ni][0] + b0, 0.f),
                                       fmaxf(acc[mi][ni][1] + b1, 0.f));
                *reinterpret_cast<float2*>(&X[(size_t)r0 * 128 + c]) = o;
            }
            if (r0 + 8 < N_NODES) {
                float2 o = make_float2(fmaxf(acc[mi][ni][2] + b0, 0.f),
                                       fmaxf(acc[mi][ni][3] + b1, 0.f));
                *reinterpret_cast<float2*>(&X[(size_t)(r0 + 8) * 128 + c]) = o;
            }
        }
    }
}

// ---------------- fused layer: phase1 [P | agg_init], phase2 y = P @ wl -----
// BM=64; P kept pre-split fragment-major in dynamic SMEM; 2 CTAs/SM.
template<int IND, bool HAS_RN>
__global__ __launch_bounds__(256, 2) void fused_layer(
    const float* __restrict__ Xin, const float* __restrict__ rn,
    const float* __restrict__ wp, const float* __restrict__ bp,
    const float* __restrict__ wr, const float* __restrict__ bl,
    const float* __restrict__ wl,
    float* __restrict__ agg, float* __restrict__ y)
{
    constexpr int BN1 = IND + 64, NI1 = BN1 / 32;
    extern __shared__ uint32_t sh[];
    uint32_t* Ah = sh;                       // 16*64
    uint32_t* Al = Ah + 16 * 64;             // 16*64
    uint32_t* Bh = Al + 16 * 64;             // 16*BN1
    uint32_t* Bl = Bh + 16 * BN1;            // 16*BN1
    uint32_t* Ph = Bl + 16 * BN1;            // IND*64 (frag-major per 16-k tile)
    uint32_t* Pl = Ph + IND * 64;            // IND*64
    const int tid = threadIdx.x, lane = tid & 31, wid = tid >> 5;
    const int gid = lane >> 2, tig = lane & 3;
    const int wm2 = wid & 1;
    const int wn1 = (wid >> 1) * (BN1 / 4);
    const int wn1_8 = wn1 >> 3;
    const int m0 = blockIdx.x * 64;

    // ---- phase 1: [P | agg_init] = [relu(A@wp+bp) | A@wr+bl] ----
    {
        float acc[2][NI1][4] = {};
        for (int k0 = 0; k0 < IND; k0 += 16) {
#pragma unroll
            for (int i = 0; i < 4; i++) {
                int idx = tid + i * 256; int m = idx >> 4, k = idx & 15;
                int mg = m0 + m, kg = k0 + k;
                float v = 0.f;
                if (mg < N_NODES) {
                    v = Xin[(size_t)mg * IND + kg];
                    if (HAS_RN) v *= rn[mg];
                }
                uint32_t h, l; split_tf32(v, h, l);
                int s = slotA(k, m);
                Ah[s] = h; Al[s] = l;
            }
#pragma unroll
            for (int i = 0; i < BN1 / 16; i++) {
                int idx = tid + i * 256; int k = idx / BN1, n = idx % BN1;
                int kg = k0 + k;
                float v = (n < IND) ? wp[kg * IND + n] : wr[kg * 64 + (n - IND)];
                uint32_t h, l; split_tf32(v, h, l);
                int s = slotB(k, n);
                Bh[s] = h; Bl[s] = l;
            }
            __syncthreads();
            mma_ktile<NI1>(Ah, Al, Bh, Bl, wm2, wn1_8, lane, acc);
            __syncthreads();
        }

        // epilogue: P (pre-split, fragment-major) -> SMEM, agg-init -> global
#pragma unroll
        for (int mi = 0; mi < 2; mi++) {
            int lr0 = wm2 * 32 + mi * 16 + gid;
#pragma unroll
            for (int ni = 0; ni < NI1; ni++) {
                int c = wn1 + ni * 8 + 2 * tig;
                float b0, b1;
                if (c < IND) { b0 = bp[c]; b1 = bp[c + 1]; }
                else         { b0 = bl[c - IND]; b1 = bl[c - IND + 1]; }
#pragma unroll
                for (int h = 0; h < 2; h++) {
                    int lr = lr0 + h * 8;
                    float v0 = acc[mi][ni][2 * h]     + b0;
                    float v1 = acc[mi][ni][2 * h + 1] + b1;
                    if (c < IND) {
                        uint32_t h0, l0, h1, l1;
                        split_tf32(fmaxf(v0, 0.f), h0, l0);
                        split_tf32(fmaxf(v1, 0.f), h1, l1);
                        // P is the A operand of phase 2: k-index = c, m-index = lr
                        int t0 = (c >> 4) * 1024 + slotA(c & 15, lr);
                        int t1 = ((c + 1) >> 4) * 1024 + slotA((c + 1) & 15, lr);
                        Ph[t0] = h0; Pl[t0] = l0;
                        Ph[t1] = h1; Pl[t1] = l1;
                    } else {
                        int r = m0 + lr;
                        if (r < N_NODES) {
                            float2 o = make_float2(v0, v1);
                            *reinterpret_cast<float2*>(&agg[(size_t)r * 64 + (c - IND)]) = o;
                        }
                    }
                }
            }
        }
    }
    __syncthreads();

    // ---- phase 2: y = P @ wl (BN=64, NI=2) ----
    {
        constexpr int NI2 = 2;
        const int wn2 = (wid >> 1) * 16;
        const int wn2_8 = wn2 >> 3;
        float acc[2][NI2][4] = {};
        for (int k0 = 0; k0 < IND; k0 += 16) {
#pragma unroll
            for (int i = 0; i < 4; i++) {
                int idx = tid + i * 256; int k = idx >> 6, n = idx & 63;
                uint32_t h, l; split_tf32(wl[(k0 + k) * 64 + n], h, l);
                int s = slotB(k, n);
                Bh[s] = h; Bl[s] = l;
            }
            __syncthreads();
            mma_ktile<NI2>(Ph + (k0 >> 4) * 1024, Pl + (k0 >> 4) * 1024,
                           Bh, Bl, wm2, wn2_8, lane, acc);
            __syncthreads();
        }
#pragma unroll
        for (int mi = 0; mi < 2; mi++) {
            int r0 = m0 + wm2 * 32 + mi * 16 + gid;
#pragma unroll
            for (int ni = 0; ni < NI2; ni++) {
                int c = wn2 + ni * 8 + 2 * tig;
                if (r0 < N_NODES) {
                    float2 o = make_float2(acc[mi][ni][0], acc[mi][ni][1]);
                    *reinterpret_cast<float2*>(&y[(size_t)r0 * 64 + c]) = o;
                }
                if (r0 + 8 < N_NODES) {
                    float2 o = make_float2(acc[mi][ni][2], acc[mi][ni][3]);
                    *reinterpret_cast<float2*>(&y[(size_t)(r0 + 8) * 64 + c]) = o;
                }
            }
        }
    }
}

// ---------------- CSR gather + fused rownorm (+ optional pooling) ----------
template<bool DO_POOL>
__global__ __launch_bounds__(256) void gather_kernel(const float* __restrict__ y,
                                                     float* __restrict__ agg,
                                                     const int* __restrict__ batch) {
    int gw = (blockIdx.x * blockDim.x + threadIdx.x) >> 5;
    int lane = threadIdx.x & 31;
    if (gw >= N_NODES) return;
    int beg = g_off[gw], end = g_off[gw + 1];
    float s0 = 0.f, s1 = 0.f;
    int i = beg;
    for (; i + 2 <= end; i += 2) {
        int sA = g_elist[i], sB = g_elist[i + 1];
        const float* pA = y + (size_t)sA * 64;
        const float* pB = y + (size_t)sB * 64;
        float a0 = pA[lane], a1 = pA[lane + 32];
        float b0 = pB[lane], b1 = pB[lane + 32];
        s0 += a0 + b0; s1 += a1 + b1;
    }
    if (i < end) {
        const float* pA = y + (size_t)g_elist[i] * 64;
        s0 += pA[lane]; s1 += pA[lane + 32];
    }
    float di = g_deg[gw];
    float a0 = agg[(size_t)gw * 64 + lane]      + di * s0;
    float a1 = agg[(size_t)gw * 64 + lane + 32] + di * s1;
    agg[(size_t)gw * 64 + lane]      = a0;
    agg[(size_t)gw * 64 + lane + 32] = a1;

    float ss = a0 * a0 + a1 * a1;
#pragma unroll
    for (int off = 16; off > 0; off >>= 1) ss += __shfl_xor_sync(0xffffffffu, ss, off);
    float rn = 1.f / fmaxf(sqrtf(ss), 1e-12f);
    if (lane == 0) g_rn[gw] = rn;

    if (DO_POOL) {
        float v0 = a0 * rn, v1 = a1 * rn;
        int b = batch[gw];
        atomicMax(&g_gmax[b * 64 + lane],      fenc(v0));
        atomicMax(&g_gmax[b * 64 + lane + 32], fenc(v1));
        atomicAdd(&g_gsum[b * 64 + lane],      v0);
        atomicAdd(&g_gsum[b * 64 + lane + 32], v1);
        if (lane == 0) atomicAdd(&g_cnt[b], 1.f);
    }
}

__global__ void final_kernel(const float* __restrict__ pw, const float* __restrict__ pb,
                             float* __restrict__ out) {
    int b = threadIdx.x / 32, lane = threadIdx.x % 32;
    if (b >= NBATCH) return;
    float c = fmaxf(g_cnt[b], 1.f);
    float g0 = fdec(g_gmax[b * 64 + lane])      + g_gsum[b * 64 + lane] / c;
    float g1 = fdec(g_gmax[b * 64 + lane + 32]) + g_gsum[b * 64 + lane + 32] / c;
    float ss = g0 * g0 + g1 * g1;
#pragma unroll
    for (int off = 16; off > 0; off >>= 1) ss += __shfl_xor_sync(0xffffffffu, ss, off);
    float inv = 1.f / sqrtf(ss);
    float o = g0 * inv * pw[lane] + g1 * inv * pw[lane + 32];
#pragma unroll
    for (int off = 16; off > 0; off >>= 1) o += __shfl_xor_sync(0xffffffffu, o, off);
    if (lane == 0) out[b] = o + pb[0];
}

// ---------------- launch ----------------
extern "C" void kernel_launch(void* const* d_in, const int* in_sizes, int n_in,
                              void* d_out, int out_size) {
    const float* node_feat = (const float*)d_in[0];
    const float* cfg       = (const float*)d_in[1];
    const int*   opcode    = (const int*)d_in[2];
    const int*   eidx      = (const int*)d_in[3];
    const int*   batch     = (const int*)d_in[4];
    const float* op_emb    = (const float*)d_in[5];
    const float* type_emb  = (const float*)d_in[6];
    const float* lin_w     = (const float*)d_in[7];
    const float* lin_b     = (const float*)d_in[8];
    const float* post_w    = (const float*)d_in[9];
    const float* post_b    = (const float*)d_in[10];
    const float* wp[3] = {(const float*)d_in[11], (const float*)d_in[16], (const float*)d_in[21]};
    const float* bp[3] = {(const float*)d_in[12], (const float*)d_in[17], (const float*)d_in[22]};
    const float* wl[3] = {(const float*)d_in[13], (const float*)d_in[18], (const float*)d_in[23]};
    const float* bl[3] = {(const float*)d_in[14], (const float*)d_in[19], (const float*)d_in[24]};
    const float* wr[3] = {(const float*)d_in[15], (const float*)d_in[20], (const float*)d_in[25]};
    const int* src = eidx;
    const int* dst = eidx + E_EDGES;

    float *x_, *aggA_, *aggB_, *y_, *rn_;
    cudaGetSymbolAddress((void**)&x_,    g_x);
    cudaGetSymbolAddress((void**)&aggA_, g_aggA);
    cudaGetSymbolAddress((void**)&aggB_, g_aggB);
    cudaGetSymbolAddress((void**)&y_,    g_y);
    cudaGetSymbolAddress((void**)&rn_,   g_rn);

    const int T = 256;
    const int GEMM_GRID = (N_NODES + 63) / 64;   // BM=64
    const unsigned GATH_GRID = (unsigned)(((size_t)N_NODES * 32 + T - 1) / T);

    // dynamic smem: (Ah+Al + Bh+Bl + Ph+Pl) * 4B
    const int SM128 = (2 * 16 * 64 + 2 * 16 * 192 + 2 * 128 * 64) * 4;  // 98304
    const int SM64  = (2 * 16 * 64 + 2 * 16 * 128 + 2 * 64 * 64) * 4;   // 57344
    cudaFuncSetAttribute(fused_layer<128, false>, cudaFuncAttributeMaxDynamicSharedMemorySize, SM128);
    cudaFuncSetAttribute(fused_layer<64, true>,   cudaFuncAttributeMaxDynamicSharedMemorySize, SM64);

    // order chosen so fused_layer<128> sits in the ncu-captured slot 4
    init_kernel<<<NBLK, T>>>();                                                                // 1
    deg_kernel<<<(E_EDGES + T - 1) / T, T>>>(dst);                                             // 2
    gemm_initial<<<GEMM_GRID, T>>>(node_feat, cfg, opcode, op_emb, type_emb, lin_w, lin_b, x_);// 3
    fused_layer<128, false><<<GEMM_GRID, T, SM128>>>(x_, nullptr, wp[0], bp[0], wr[0], bl[0], wl[0], aggA_, y_); // 4 (captured)
    scan1_kernel<<<NBLK, T>>>();                                                               // 5
    scan2_kernel<<<1, 1024>>>();                                                               // 6
    scan3_kernel<<<NBLK, T>>>();                                                               // 7
    fill_kernel<<<(E_EDGES + T - 1) / T, T>>>(src, dst);                                       // 8
    deginv_kernel<<<(N_NODES + T - 1) / T, T>>>();                                             // 9

    // layer 0 aggregation
    gather_kernel<false><<<GATH_GRID, T>>>(y_, aggA_, batch);

    // layer 1 (IND=64)
    fused_layer<64, true><<<GEMM_GRID, T, SM64>>>(aggA_, rn_, wp[1], bp[1], wr[1], bl[1], wl[1], aggB_, y_);
    gather_kernel<false><<<GATH_GRID, T>>>(y_, aggB_, batch);

    // layer 2 (IND=64), pooling fused into gather
    fused_layer<64, true><<<GEMM_GRID, T, SM64>>>(aggB_, rn_, wp[2], bp[2], wr[2], bl[2], wl[2], aggA_, y_);
    gather_kernel<true><<<GATH_GRID, T>>>(y_, aggA_, batch);

    final_kernel<<<1, 512>>>(post_w, post_b, (float*)d_out);
}